// round 2
// baseline (speedup 1.0000x reference)
#include <cuda_runtime.h>
#include <math.h>

#define Bz   8
#define Sq   1024
#define Dm   1024
#define Hn   16
#define HDim 64
#define Ff   4096
#define NL   6
#define NTOK (Bz*Sq)   /* 8192 tokens */

// One big scratch buffer: X,Q,K,V,T1,T2 (8192x1024 each) + H1 (8192x4096)
__device__ float g_buf[(size_t)NTOK*Dm*6 + (size_t)NTOK*Ff];

// ---------------------------------------------------------------------------
// Embedding * sqrt(D) + sinusoidal PE
// ---------------------------------------------------------------------------
__global__ void embed_kernel(const int* __restrict__ src, const float* __restrict__ emb,
                             float* __restrict__ X)
{
    int row = blockIdx.x;          // b*S + s
    int s   = row % Sq;
    int tok = src[row];
    const float* er = emb + (size_t)tok * Dm;
    float* xr = X + (size_t)row * Dm;
    #pragma unroll
    for (int e = 0; e < 4; e++) {
        int d  = threadIdx.x + e * 256;
        int j2 = (d >> 1) * 2;                       // even index of the pair
        float div = powf(10000.0f, (float)j2 / (float)Dm);
        float ang = (float)s / div;
        float pe  = (d & 1) ? cosf(ang) : sinf(ang);
        xr[d] = er[d] * 32.0f + pe;                  // sqrt(1024) = 32
    }
}

// ---------------------------------------------------------------------------
// C[M,N] = A[M,K] @ B[K,N] + bias[N]  (optional ReLU)
// 128x128x16 tiles, 256 threads, 8x8 micro-tile
// ---------------------------------------------------------------------------
__global__ __launch_bounds__(256)
void gemm_kernel(const float* __restrict__ A, const float* __restrict__ B,
                 const float* __restrict__ bias, float* __restrict__ C,
                 int M, int N, int K, int relu)
{
    __shared__ float As[16][132];   // transposed A tile (k-major), padded
    __shared__ float Bs[16][128];
    int tid = threadIdx.x;
    int tx = tid & 15, ty = tid >> 4;
    int bn = blockIdx.x * 128, bm = blockIdx.y * 128;

    float acc[8][8];
    #pragma unroll
    for (int i = 0; i < 8; i++)
        #pragma unroll
        for (int j = 0; j < 8; j++) acc[i][j] = 0.f;

    for (int k0 = 0; k0 < K; k0 += 16) {
        #pragma unroll
        for (int v = 0; v < 2; v++) {                 // A tile: 128x16
            int idx = tid + v * 256;
            int row = idx >> 2;
            int kc  = (idx & 3) << 2;
            float4 a = *(const float4*)(A + (size_t)(bm + row) * K + k0 + kc);
            As[kc + 0][row] = a.x; As[kc + 1][row] = a.y;
            As[kc + 2][row] = a.z; As[kc + 3][row] = a.w;
        }
        #pragma unroll
        for (int v = 0; v < 2; v++) {                 // B tile: 16x128
            int idx = tid + v * 256;
            int row = idx >> 5;
            int c   = (idx & 31) << 2;
            *(float4*)&Bs[row][c] = *(const float4*)(B + (size_t)(k0 + row) * N + bn + c);
        }
        __syncthreads();
        #pragma unroll
        for (int kk = 0; kk < 16; kk++) {
            float a[8], b[8];
            *(float4*)(a)     = *(float4*)&As[kk][ty * 8];
            *(float4*)(a + 4) = *(float4*)&As[kk][ty * 8 + 4];
            *(float4*)(b)     = *(float4*)&Bs[kk][tx * 8];
            *(float4*)(b + 4) = *(float4*)&Bs[kk][tx * 8 + 4];
            #pragma unroll
            for (int i = 0; i < 8; i++)
                #pragma unroll
                for (int j = 0; j < 8; j++)
                    acc[i][j] = fmaf(a[i], b[j], acc[i][j]);
        }
        __syncthreads();
    }

    #pragma unroll
    for (int i = 0; i < 8; i++) {
        int row = bm + ty * 8 + i;
        #pragma unroll
        for (int j4 = 0; j4 < 2; j4++) {
            int col = bn + tx * 8 + j4 * 4;
            float4 r;
            r.x = acc[i][j4*4+0] + bias[col+0];
            r.y = acc[i][j4*4+1] + bias[col+1];
            r.z = acc[i][j4*4+2] + bias[col+2];
            r.w = acc[i][j4*4+3] + bias[col+3];
            if (relu) {
                r.x = fmaxf(r.x, 0.f); r.y = fmaxf(r.y, 0.f);
                r.z = fmaxf(r.z, 0.f); r.w = fmaxf(r.w, 0.f);
            }
            *(float4*)(C + (size_t)row * N + col) = r;
        }
    }
}

// ---------------------------------------------------------------------------
// Flash-style attention: one block = (b, h, 64-row q tile), online softmax
// ---------------------------------------------------------------------------
#define SSTR 65
__global__ __launch_bounds__(256)
void attn_kernel(const float* __restrict__ Q, const float* __restrict__ Kd,
                 const float* __restrict__ V, const int* __restrict__ mask,
                 float* __restrict__ O)
{
    extern __shared__ float sm[];
    float* Qs = sm;
    float* Ks = Qs + 64 * SSTR;
    float* Vs = Ks + 64 * SSTR;
    float* Ps = Vs + 64 * SSTR;

    int q0 = blockIdx.x * 64;
    int h  = blockIdx.y, b = blockIdx.z;
    int tid = threadIdx.x;
    int tx = tid & 15, ty = tid >> 4;
    size_t baseq = ((size_t)b * Sq + q0) * Dm + h * HDim;

    #pragma unroll
    for (int e = 0; e < 16; e++) {
        int idx = e * 256 + tid;
        int r = idx >> 6, c = idx & 63;
        Qs[r * SSTR + c] = Q[baseq + (size_t)r * Dm + c];
    }

    float mrow[4], lrow[4], acc[4][4];
    #pragma unroll
    for (int i = 0; i < 4; i++) {
        mrow[i] = -1e30f; lrow[i] = 0.f;
        #pragma unroll
        for (int j = 0; j < 4; j++) acc[i][j] = 0.f;
    }
    const int* mrowp = mask + (size_t)b * Sq;

    for (int k0 = 0; k0 < Sq; k0 += 64) {
        __syncthreads();   // protect K/V/P reuse across iterations
        size_t basek = ((size_t)b * Sq + k0) * Dm + h * HDim;
        #pragma unroll
        for (int e = 0; e < 16; e++) {
            int idx = e * 256 + tid;
            int r = idx >> 6, c = idx & 63;
            Ks[r * SSTR + c] = Kd[basek + (size_t)r * Dm + c];
            Vs[r * SSTR + c] = V [basek + (size_t)r * Dm + c];
        }
        __syncthreads();

        float s[4][4];
        #pragma unroll
        for (int i = 0; i < 4; i++)
            #pragma unroll
            for (int j = 0; j < 4; j++) s[i][j] = 0.f;
        #pragma unroll 8
        for (int kk = 0; kk < 64; kk++) {
            float aq[4], bk[4];
            #pragma unroll
            for (int i = 0; i < 4; i++) aq[i] = Qs[(ty*4+i)*SSTR + kk];
            #pragma unroll
            for (int j = 0; j < 4; j++) bk[j] = Ks[(tx*4+j)*SSTR + kk];
            #pragma unroll
            for (int i = 0; i < 4; i++)
                #pragma unroll
                for (int j = 0; j < 4; j++)
                    s[i][j] = fmaf(aq[i], bk[j], s[i][j]);
        }
        // scale + mask
        #pragma unroll
        for (int j = 0; j < 4; j++) {
            int kc = k0 + tx * 4 + j;
            bool msk = (mrowp[kc] == 0);
            #pragma unroll
            for (int i = 0; i < 4; i++)
                s[i][j] = msk ? -1e10f : s[i][j] * 0.125f;
        }
        // online softmax (row stats reduced across the 16 tx lanes)
        #pragma unroll
        for (int i = 0; i < 4; i++) {
            float tm = fmaxf(fmaxf(s[i][0], s[i][1]), fmaxf(s[i][2], s[i][3]));
            #pragma unroll
            for (int off = 8; off >= 1; off >>= 1)
                tm = fmaxf(tm, __shfl_xor_sync(0xffffffffu, tm, off, 16));
            float nm   = fmaxf(mrow[i], tm);
            float corr = __expf(mrow[i] - nm);
            float rs = 0.f;
            #pragma unroll
            for (int j = 0; j < 4; j++) { s[i][j] = __expf(s[i][j] - nm); rs += s[i][j]; }
            #pragma unroll
            for (int off = 8; off >= 1; off >>= 1)
                rs += __shfl_xor_sync(0xffffffffu, rs, off, 16);
            lrow[i] = lrow[i] * corr + rs;
            mrow[i] = nm;
            #pragma unroll
            for (int j = 0; j < 4; j++) acc[i][j] *= corr;
        }
        #pragma unroll
        for (int i = 0; i < 4; i++)
            #pragma unroll
            for (int j = 0; j < 4; j++)
                Ps[(ty*4+i)*SSTR + tx*4+j] = s[i][j];
        __syncthreads();
        #pragma unroll 8
        for (int kk = 0; kk < 64; kk++) {
            float pv[4], vv[4];
            #pragma unroll
            for (int i = 0; i < 4; i++) pv[i] = Ps[(ty*4+i)*SSTR + kk];
            #pragma unroll
            for (int j = 0; j < 4; j++) vv[j] = Vs[kk*SSTR + tx*4+j];
            #pragma unroll
            for (int i = 0; i < 4; i++)
                #pragma unroll
                for (int j = 0; j < 4; j++)
                    acc[i][j] = fmaf(pv[i], vv[j], acc[i][j]);
        }
    }

    #pragma unroll
    for (int i = 0; i < 4; i++) {
        float inv = 1.f / lrow[i];
        float4 r;
        r.x = acc[i][0]*inv; r.y = acc[i][1]*inv;
        r.z = acc[i][2]*inv; r.w = acc[i][3]*inv;
        *(float4*)(O + baseq + (size_t)(ty*4+i) * Dm + tx*4) = r;
    }
}

// ---------------------------------------------------------------------------
// dst = LayerNorm(x + t) * g + b        (one block per token row of 1024)
// ---------------------------------------------------------------------------
__device__ __forceinline__ float block_reduce_sum(float v, float* red)
{
    #pragma unroll
    for (int o = 16; o > 0; o >>= 1) v += __shfl_xor_sync(0xffffffffu, v, o);
    int w = threadIdx.x >> 5;
    if ((threadIdx.x & 31) == 0) red[w] = v;
    __syncthreads();
    if (threadIdx.x < 32) {
        float r = (threadIdx.x < 8) ? red[threadIdx.x] : 0.f;
        #pragma unroll
        for (int o = 4; o > 0; o >>= 1) r += __shfl_xor_sync(0xffffffffu, r, o);
        if (threadIdx.x == 0) red[0] = r;
    }
    __syncthreads();
    float r = red[0];
    __syncthreads();
    return r;
}

__global__ __launch_bounds__(256)
void add_ln_kernel(const float* __restrict__ x, const float* __restrict__ t,
                   const float* __restrict__ g, const float* __restrict__ bt,
                   float* __restrict__ dst)
{
    __shared__ float red[8];
    size_t base = (size_t)blockIdx.x * Dm;
    float v[4]; float s = 0.f;
    #pragma unroll
    for (int e = 0; e < 4; e++) {
        int c = threadIdx.x + e * 256;
        v[e] = x[base + c] + t[base + c];
        s += v[e];
    }
    s = block_reduce_sum(s, red);
    float mu = s * (1.0f / Dm);
    float q = 0.f;
    #pragma unroll
    for (int e = 0; e < 4; e++) { float d = v[e] - mu; q += d * d; }
    q = block_reduce_sum(q, red);
    float inv = rsqrtf(q * (1.0f / Dm) + 1e-5f);
    #pragma unroll
    for (int e = 0; e < 4; e++) {
        int c = threadIdx.x + e * 256;
        dst[base + c] = (v[e] - mu) * inv * g[c] + bt[c];
    }
}

// ---------------------------------------------------------------------------
extern "C" void kernel_launch(void* const* d_in, const int* in_sizes, int n_in,
                              void* d_out, int out_size)
{
    const int*   src = (const int*)d_in[0];
    const int*   msk = (const int*)d_in[1];
    const float* emb = (const float*)d_in[2];
    const float* Wq  = (const float*)d_in[3];
    const float* bq  = (const float*)d_in[4];
    const float* Wk  = (const float*)d_in[5];
    const float* bk  = (const float*)d_in[6];
    const float* Wv  = (const float*)d_in[7];
    const float* bv  = (const float*)d_in[8];
    const float* Wo  = (const float*)d_in[9];
    const float* bo  = (const float*)d_in[10];
    const float* g1  = (const float*)d_in[11];
    const float* b1n = (const float*)d_in[12];
    const float* W1  = (const float*)d_in[13];
    const float* b1  = (const float*)d_in[14];
    const float* W2  = (const float*)d_in[15];
    const float* b2  = (const float*)d_in[16];
    const float* g2  = (const float*)d_in[17];
    const float* b2n = (const float*)d_in[18];
    float* out = (float*)d_out;

    float* base = nullptr;
    cudaGetSymbolAddress((void**)&base, g_buf);
    float* X  = base;
    float* Qb = base + (size_t)NTOK * Dm;
    float* Kb = base + (size_t)NTOK * Dm * 2;
    float* Vb = base + (size_t)NTOK * Dm * 3;
    float* T1 = base + (size_t)NTOK * Dm * 4;
    float* T2 = base + (size_t)NTOK * Dm * 5;
    float* H1 = base + (size_t)NTOK * Dm * 6;

    const int ATTN_SMEM = 4 * 64 * SSTR * 4;   // 66560 bytes
    cudaFuncSetAttribute((const void*)attn_kernel,
                         cudaFuncAttributeMaxDynamicSharedMemorySize, ATTN_SMEM);

    embed_kernel<<<NTOK, 256>>>(src, emb, X);

    dim3 gD(Dm / 128, NTOK / 128);   // (8, 64)
    dim3 gF(Ff / 128, NTOK / 128);   // (32, 64)
    dim3 gA(Sq / 64, Hn, Bz);        // (16, 16, 8)

    for (int l = 0; l < NL; l++) {
        size_t oDD = (size_t)l * Dm * Dm;
        size_t oD  = (size_t)l * Dm;
        size_t oDF = (size_t)l * Dm * Ff;
        size_t oF  = (size_t)l * Ff;

        gemm_kernel<<<gD, 256>>>(X,  Wq + oDD, bq + oD, Qb, NTOK, Dm, Dm, 0);
        gemm_kernel<<<gD, 256>>>(X,  Wk + oDD, bk + oD, Kb, NTOK, Dm, Dm, 0);
        gemm_kernel<<<gD, 256>>>(X,  Wv + oDD, bv + oD, Vb, NTOK, Dm, Dm, 0);
        attn_kernel<<<gA, 256, ATTN_SMEM>>>(Qb, Kb, Vb, msk, T1);
        gemm_kernel<<<gD, 256>>>(T1, Wo + oDD, bo + oD, T2, NTOK, Dm, Dm, 0);
        add_ln_kernel<<<NTOK, 256>>>(X, T2, g1 + oD, b1n + oD, X);
        gemm_kernel<<<gF, 256>>>(X,  W1 + oDF, b1 + oF, H1, NTOK, Ff, Dm, 1);
        gemm_kernel<<<gD, 256>>>(H1, W2 + oDF, b2 + oD, T2, NTOK, Dm, Ff, 0);
        add_ln_kernel<<<NTOK, 256>>>(X, T2, g2 + oD, b2n + oD, (l == NL - 1) ? out : X);
    }
}